// round 1
// baseline (speedup 1.0000x reference)
#include <cuda_runtime.h>

#define BB 4
#define QN 128
#define KN 1024
#define DD 512     // DQ == DK == DV
#define HH 256

// Scratch (allocation-free rule: __device__ globals)
__device__ float g_qp[BB * QN * HH];       // [512][256]
__device__ float g_kp[BB * KN * HH];       // [4096][256]
__device__ float g_scores[BB * QN * KN];   // [512][1024], softmax in-place -> attn

// ---------------------------------------------------------------------------
// Projection GEMM: C[M,256] = A[M,512] @ W[512,256]
// 64x64 tile, 256 threads, 4x4 per thread, K-tile 16.
// outSel: 0 -> g_qp, 1 -> g_kp (with valid_lens row-tile skip, 1024 rows/batch)
// ---------------------------------------------------------------------------
__global__ __launch_bounds__(256) void proj_gemm(
    const float* __restrict__ A, const float* __restrict__ W,
    int outSel, const int* __restrict__ vlen)
{
    const int m0 = blockIdx.x * 64;
    const int n0 = blockIdx.y * 64;
    if (outSel == 1 && vlen) {
        int b = m0 >> 10;               // 1024 rows per batch
        if ((m0 & 1023) >= vlen[b]) return;   // whole tile masked
    }
    float* __restrict__ C = outSel ? g_kp : g_qp;

    __shared__ __align__(16) float As[16][68];
    __shared__ __align__(16) float Bs[16][68];

    const int tid = threadIdx.x;
    const int tx = tid & 15;       // 0..15 -> n
    const int ty = tid >> 4;       // 0..15 -> m

    float acc[4][4] = {};

    for (int k0 = 0; k0 < DD; k0 += 16) {
        // A tile 64x16 -> transposed As[k][m]
        {
            int row = tid >> 2;                 // 0..63
            int c4  = tid & 3;                  // 0..3
            float4 v = *(const float4*)&A[(size_t)(m0 + row) * DD + k0 + c4 * 4];
            As[c4 * 4 + 0][row] = v.x;
            As[c4 * 4 + 1][row] = v.y;
            As[c4 * 4 + 2][row] = v.z;
            As[c4 * 4 + 3][row] = v.w;
        }
        // W tile 16x64 -> Bs[k][n]
        {
            int n4 = tid & 15;
            int kk = tid >> 4;
            float4 v = *(const float4*)&W[(size_t)(k0 + kk) * HH + n0 + n4 * 4];
            *(float4*)&Bs[kk][n4 * 4] = v;
        }
        __syncthreads();
        #pragma unroll
        for (int kk = 0; kk < 16; kk++) {
            float4 a = *(const float4*)&As[kk][ty * 4];
            float4 b = *(const float4*)&Bs[kk][tx * 4];
            float av[4] = {a.x, a.y, a.z, a.w};
            float bv[4] = {b.x, b.y, b.z, b.w};
            #pragma unroll
            for (int i = 0; i < 4; i++)
                #pragma unroll
                for (int j = 0; j < 4; j++)
                    acc[i][j] = fmaf(av[i], bv[j], acc[i][j]);
        }
        __syncthreads();
    }

    #pragma unroll
    for (int i = 0; i < 4; i++) {
        float4 o = make_float4(acc[i][0], acc[i][1], acc[i][2], acc[i][3]);
        *(float4*)&C[(size_t)(m0 + ty * 4 + i) * HH + n0 + tx * 4] = o;
    }
}

// ---------------------------------------------------------------------------
// Scores: s[b,q,k] = sum_h wv[h] * tanh(qp[b,q,h] + kp[b,k,h])
// grid: (ktile 8) x (qtile 16) x (b 4); block 256 = 8 warps (q) x 32 lanes (k)
// ---------------------------------------------------------------------------
__global__ __launch_bounds__(256) void scores_kernel(
    const float* __restrict__ wv, const int* __restrict__ vlen)
{
    const int b  = blockIdx.z;
    const int q0 = blockIdx.y * 8;
    const int k0 = blockIdx.x * 128;
    const int vl = vlen[b];
    if (k0 >= vl) return;

    __shared__ __align__(16) float qs[8][HH];      // 8 KB
    __shared__ __align__(16) float wvs[HH];        // 1 KB
    __shared__ float kst[HH][33];                  // 33 KB, transposed k-tile

    const int tid  = threadIdx.x;
    const int lane = tid & 31;
    const int w    = tid >> 5;

    // load qs (2048 floats) + wv
    const float* qpB = g_qp + (size_t)(b * QN + q0) * HH;
    #pragma unroll
    for (int i = 0; i < 2; i++)
        ((float4*)qs)[tid + i * 256] = ((const float4*)qpB)[tid + i * 256];
    if (tid < 64)
        ((float4*)wvs)[tid] = ((const float4*)wv)[tid];

    const int q = w;       // warp -> query
    const int k = lane;    // lane -> key within 32-chunk

    for (int kc = k0; kc < k0 + 128; kc += 32) {
        if (kc >= vl) break;   // uniform across block
        __syncthreads();
        // Transposed load: kst[h][kk] from g_kp[(b*KN+kc+kk)*HH + h]
        // lane -> (h4 = (lane&7)+8*i, kk = (lane>>3)+4*w): coalesced 128B groups,
        // and STS bank = (4*h4 + j + kk) % 32 is conflict-free.
        const float* kpB = g_kp + (size_t)(b * KN + kc) * HH;
        {
            int kk = (lane >> 3) + 4 * w;   // 0..31
            int hb = (lane & 7);            // 0..7
            #pragma unroll
            for (int i = 0; i < 8; i++) {
                int h4 = hb + 8 * i;        // 0..63
                float4 v = ((const float4*)(kpB + (size_t)kk * HH))[h4];
                kst[h4 * 4 + 0][kk] = v.x;
                kst[h4 * 4 + 1][kk] = v.y;
                kst[h4 * 4 + 2][kk] = v.z;
                kst[h4 * 4 + 3][kk] = v.w;
            }
        }
        __syncthreads();

        float acc = 0.f;
        #pragma unroll 4
        for (int h0 = 0; h0 < HH; h0 += 8) {
            float4 a0 = *(const float4*)&qs[q][h0];
            float4 a1 = *(const float4*)&qs[q][h0 + 4];
            float4 w0 = *(const float4*)&wvs[h0];
            float4 w1 = *(const float4*)&wvs[h0 + 4];
            float av[8] = {a0.x, a0.y, a0.z, a0.w, a1.x, a1.y, a1.z, a1.w};
            float wva[8] = {w0.x, w0.y, w0.z, w0.w, w1.x, w1.y, w1.z, w1.w};
            #pragma unroll
            for (int j = 0; j < 8; j++) {
                float x = av[j] + kst[h0 + j][k];
                float t;
                asm("tanh.approx.f32 %0, %1;" : "=f"(t) : "f"(x));
                acc = fmaf(wva[j], t, acc);
            }
        }
        g_scores[(size_t)(b * QN + q0 + q) * KN + kc + k] = acc;
    }
}

// ---------------------------------------------------------------------------
// Softmax in place on g_scores (masked -> exact 0). One warp per row.
// ---------------------------------------------------------------------------
__global__ __launch_bounds__(256) void softmax_kernel(const int* __restrict__ vlen)
{
    const int row  = blockIdx.x * 8 + (threadIdx.x >> 5);   // 0..511
    const int lane = threadIdx.x & 31;
    const int b    = row >> 7;
    const int vl   = vlen[b];
    float* s = g_scores + (size_t)row * KN;

    float vals[32];
    float mx = -1e30f;
    #pragma unroll
    for (int i = 0; i < 32; i++) {
        int kk = lane + i * 32;
        float v = (kk < vl) ? s[kk] : -1e30f;
        vals[i] = v;
        mx = fmaxf(mx, v);
    }
    #pragma unroll
    for (int o = 16; o; o >>= 1) mx = fmaxf(mx, __shfl_xor_sync(0xffffffffu, mx, o));

    float sum = 0.f;
    #pragma unroll
    for (int i = 0; i < 32; i++) {
        float e = (vals[i] > -1e29f) ? __expf(vals[i] - mx) : 0.f;
        vals[i] = e;
        sum += e;
    }
    #pragma unroll
    for (int o = 16; o; o >>= 1) sum += __shfl_xor_sync(0xffffffffu, sum, o);

    float r = 1.f / sum;
    #pragma unroll
    for (int i = 0; i < 32; i++) s[lane + i * 32] = vals[i] * r;
}

// ---------------------------------------------------------------------------
// AV GEMM: out[b][128][512] = attn[b][128][1024] @ V[b][1024][512]
// reduction clipped to ceil(vlen/16)*16 (attn is exactly 0 beyond vlen)
// ---------------------------------------------------------------------------
__global__ __launch_bounds__(256) void av_gemm(
    const float* __restrict__ V, float* __restrict__ out,
    const int* __restrict__ vlen)
{
    const int b  = blockIdx.z;
    const int m0 = blockIdx.x * 64;
    const int n0 = blockIdx.y * 64;
    const int vl = vlen[b];
    const int kcap = min(KN, (vl + 15) & ~15);

    const float* __restrict__ A  = g_scores + (size_t)b * QN * KN;
    const float* __restrict__ Bv = V + (size_t)b * KN * DD;
    float* __restrict__ C        = out + (size_t)b * QN * DD;

    __shared__ __align__(16) float As[16][68];
    __shared__ __align__(16) float Bs[16][68];

    const int tid = threadIdx.x;
    const int tx = tid & 15;
    const int ty = tid >> 4;

    float acc[4][4] = {};

    for (int k0 = 0; k0 < kcap; k0 += 16) {
        {
            int row = tid >> 2;
            int c4  = tid & 3;
            float4 v = *(const float4*)&A[(size_t)(m0 + row) * KN + k0 + c4 * 4];
            As[c4 * 4 + 0][row] = v.x;
            As[c4 * 4 + 1][row] = v.y;
            As[c4 * 4 + 2][row] = v.z;
            As[c4 * 4 + 3][row] = v.w;
        }
        {
            int n4 = tid & 15;
            int kk = tid >> 4;
            float4 v = *(const float4*)&Bv[(size_t)(k0 + kk) * DD + n0 + n4 * 4];
            *(float4*)&Bs[kk][n4 * 4] = v;
        }
        __syncthreads();
        #pragma unroll
        for (int kk = 0; kk < 16; kk++) {
            float4 a = *(const float4*)&As[kk][ty * 4];
            float4 bq = *(const float4*)&Bs[kk][tx * 4];
            float av[4] = {a.x, a.y, a.z, a.w};
            float bv2[4] = {bq.x, bq.y, bq.z, bq.w};
            #pragma unroll
            for (int i = 0; i < 4; i++)
                #pragma unroll
                for (int j = 0; j < 4; j++)
                    acc[i][j] = fmaf(av[i], bv2[j], acc[i][j]);
        }
        __syncthreads();
    }

    #pragma unroll
    for (int i = 0; i < 4; i++) {
        float4 o = make_float4(acc[i][0], acc[i][1], acc[i][2], acc[i][3]);
        *(float4*)&C[(size_t)(m0 + ty * 4 + i) * DD + n0 + tx * 4] = o;
    }
}

// ---------------------------------------------------------------------------
extern "C" void kernel_launch(void* const* d_in, const int* in_sizes, int n_in,
                              void* d_out, int out_size)
{
    (void)in_sizes; (void)n_in; (void)out_size;
    const float* queries = (const float*)d_in[0];   // [4,128,512]
    const float* keys    = (const float*)d_in[1];   // [4,1024,512]
    const float* values  = (const float*)d_in[2];   // [4,1024,512]
    const int*   vlen    = (const int*)d_in[3];     // [4]
    const float* Wq      = (const float*)d_in[4];   // [512,256]
    const float* Wk      = (const float*)d_in[5];   // [512,256]
    const float* wv      = (const float*)d_in[6];   // [256]
    float* out = (float*)d_out;                     // [4,128,512]

    proj_gemm<<<dim3(8, 4), 256>>>(queries, Wq, 0, nullptr);       // qp [512,256]
    proj_gemm<<<dim3(64, 4), 256>>>(keys, Wk, 1, vlen);            // kp [4096,256]
    scores_kernel<<<dim3(8, 16, 4), 256>>>(wv, vlen);
    softmax_kernel<<<64, 256>>>(vlen);
    av_gemm<<<dim3(2, 8, 4), 256>>>(values, out, vlen);
}

// round 4
// speedup vs baseline: 2.1253x; 2.1253x over previous
#include <cuda_runtime.h>

#define BB 4
#define QN 128
#define KN 1024
#define DD 512     // DQ == DK == DV
#define HH 256
#define NSPLIT 4
#define KSPLIT (KN / NSPLIT)   // 256

// Scratch (allocation-free rule: __device__ globals)
__device__ float g_qp[BB * QN * HH];                 // [512][256]
__device__ float g_kp[BB * KN * HH];                 // [4096][256]
__device__ float g_scores[BB * QN * KN];             // [512][1024] -> attn in place
__device__ float g_avp[NSPLIT][BB * QN * DD];        // split-K partials, 4 MB

// ---------------------------------------------------------------------------
// Combined projection GEMM over M = 512 (queries) + 4096 (keys) rows.
// C[M,256] = A[M,512] @ W[512,256]; 64x64 tile, 256 thr, 4x4/thread, K-tile 16
// Key tiles fully beyond valid_len are skipped.
// ---------------------------------------------------------------------------
__global__ __launch_bounds__(256) void proj_gemm(
    const float* __restrict__ queries, const float* __restrict__ keys,
    const float* __restrict__ Wq, const float* __restrict__ Wk,
    const int* __restrict__ vlen)
{
    const int m0g = blockIdx.x * 64;          // 0..4544
    const int n0  = blockIdx.y * 64;

    const float* A;
    const float* W;
    float* C;
    int m0;
    if (m0g < BB * QN) {                      // query rows
        A = queries; W = Wq; C = g_qp; m0 = m0g;
    } else {                                  // key rows
        m0 = m0g - BB * QN;
        int b = m0 >> 10;                     // 1024 rows per batch
        if ((m0 & 1023) >= vlen[b]) return;   // whole tile masked
        A = keys; W = Wk; C = g_kp;
    }

    __shared__ __align__(16) float As[16][68];
    __shared__ __align__(16) float Bs[16][68];

    const int tid = threadIdx.x;
    const int tx = tid & 15;       // n
    const int ty = tid >> 4;       // m

    float acc[4][4] = {};

    for (int k0 = 0; k0 < DD; k0 += 16) {
        {
            int row = tid >> 2;
            int c4  = tid & 3;
            float4 v = *(const float4*)&A[(size_t)(m0 + row) * DD + k0 + c4 * 4];
            As[c4 * 4 + 0][row] = v.x;
            As[c4 * 4 + 1][row] = v.y;
            As[c4 * 4 + 2][row] = v.z;
            As[c4 * 4 + 3][row] = v.w;
        }
        {
            int n4 = tid & 15;
            int kk = tid >> 4;
            float4 v = *(const float4*)&W[(size_t)(k0 + kk) * HH + n0 + n4 * 4];
            *(float4*)&Bs[kk][n4 * 4] = v;
        }
        __syncthreads();
        #pragma unroll
        for (int kk = 0; kk < 16; kk++) {
            float4 a = *(const float4*)&As[kk][ty * 4];
            float4 b = *(const float4*)&Bs[kk][tx * 4];
            float av[4] = {a.x, a.y, a.z, a.w};
            float bv[4] = {b.x, b.y, b.z, b.w};
            #pragma unroll
            for (int i = 0; i < 4; i++)
                #pragma unroll
                for (int j = 0; j < 4; j++)
                    acc[i][j] = fmaf(av[i], bv[j], acc[i][j]);
        }
        __syncthreads();
    }

    #pragma unroll
    for (int i = 0; i < 4; i++) {
        float4 o = make_float4(acc[i][0], acc[i][1], acc[i][2], acc[i][3]);
        *(float4*)&C[(size_t)(m0 + ty * 4 + i) * HH + n0 + tx * 4] = o;
    }
}

// ---------------------------------------------------------------------------
// Scores: s[b,q,k] = sum_h wv[h] * tanh(qp[b,q,h] + kp[b,k,h])
// grid: (ktile 8) x (qtile 16) x (b 4); block 256 = 8 warps (q) x 32 lanes (k)
// ---------------------------------------------------------------------------
__global__ __launch_bounds__(256) void scores_kernel(
    const float* __restrict__ wv, const int* __restrict__ vlen)
{
    const int b  = blockIdx.z;
    const int q0 = blockIdx.y * 8;
    const int k0 = blockIdx.x * 128;
    const int vl = vlen[b];
    if (k0 >= vl) return;

    __shared__ __align__(16) float qs[8][HH];      // 8 KB
    __shared__ __align__(16) float wvs[HH];        // 1 KB
    __shared__ float kst[HH][33];                  // 33 KB, transposed k-tile

    const int tid  = threadIdx.x;
    const int lane = tid & 31;
    const int w    = tid >> 5;

    const float* qpB = g_qp + (size_t)(b * QN + q0) * HH;
    #pragma unroll
    for (int i = 0; i < 2; i++)
        ((float4*)qs)[tid + i * 256] = ((const float4*)qpB)[tid + i * 256];
    if (tid < 64)
        ((float4*)wvs)[tid] = ((const float4*)wv)[tid];

    const int q = w;
    const int k = lane;

    for (int kc = k0; kc < k0 + 128; kc += 32) {
        if (kc >= vl) break;   // uniform across block
        __syncthreads();
        const float* kpB = g_kp + (size_t)(b * KN + kc) * HH;
        {
            int kk = (lane >> 3) + 4 * w;   // 0..31
            int hb = (lane & 7);            // 0..7
            #pragma unroll
            for (int i = 0; i < 8; i++) {
                int h4 = hb + 8 * i;        // 0..63
                float4 v = ((const float4*)(kpB + (size_t)kk * HH))[h4];
                kst[h4 * 4 + 0][kk] = v.x;
                kst[h4 * 4 + 1][kk] = v.y;
                kst[h4 * 4 + 2][kk] = v.z;
                kst[h4 * 4 + 3][kk] = v.w;
            }
        }
        __syncthreads();

        float acc = 0.f;
        #pragma unroll 4
        for (int h0 = 0; h0 < HH; h0 += 8) {
            float4 a0 = *(const float4*)&qs[q][h0];
            float4 a1 = *(const float4*)&qs[q][h0 + 4];
            float4 w0 = *(const float4*)&wvs[h0];
            float4 w1 = *(const float4*)&wvs[h0 + 4];
            float av[8] = {a0.x, a0.y, a0.z, a0.w, a1.x, a1.y, a1.z, a1.w};
            float wva[8] = {w0.x, w0.y, w0.z, w0.w, w1.x, w1.y, w1.z, w1.w};
            #pragma unroll
            for (int j = 0; j < 8; j++) {
                float x = av[j] + kst[h0 + j][k];
                float t;
                asm("tanh.approx.f32 %0, %1;" : "=f"(t) : "f"(x));
                acc = fmaf(wva[j], t, acc);
            }
        }
        g_scores[(size_t)(b * QN + q0 + q) * KN + kc + k] = acc;
    }
}

// ---------------------------------------------------------------------------
// Softmax in place on g_scores (masked -> exact 0). One warp per row.
// grid 128 x block 128 (4 rows/block) for better SM coverage.
// ---------------------------------------------------------------------------
__global__ __launch_bounds__(128) void softmax_kernel(const int* __restrict__ vlen)
{
    const int row  = blockIdx.x * 4 + (threadIdx.x >> 5);   // 0..511
    const int lane = threadIdx.x & 31;
    const int b    = row >> 7;
    const int vl   = vlen[b];
    float* s = g_scores + (size_t)row * KN;

    float vals[32];
    float mx = -1e30f;
    #pragma unroll
    for (int i = 0; i < 32; i++) {
        int kk = lane + i * 32;
        float v = (kk < vl) ? s[kk] : -1e30f;
        vals[i] = v;
        mx = fmaxf(mx, v);
    }
    #pragma unroll
    for (int o = 16; o; o >>= 1) mx = fmaxf(mx, __shfl_xor_sync(0xffffffffu, mx, o));

    float sum = 0.f;
    #pragma unroll
    for (int i = 0; i < 32; i++) {
        float e = (vals[i] > -1e29f) ? __expf(vals[i] - mx) : 0.f;
        vals[i] = e;
        sum += e;
    }
    #pragma unroll
    for (int o = 16; o; o >>= 1) sum += __shfl_xor_sync(0xffffffffu, sum, o);

    float r = 1.f / sum;
    #pragma unroll
    for (int i = 0; i < 32; i++) s[lane + i * 32] = vals[i] * r;
}

// ---------------------------------------------------------------------------
// AV GEMM split-K: partial[s][b][128][512] = attn[b][:, s*256:(s+1)*256] @ V slice
// grid: (m 2, n 8, b*NSPLIT 16); reduction clipped to vlen (attn==0 beyond).
// ---------------------------------------------------------------------------
__global__ __launch_bounds__(256) void av_gemm(
    const float* __restrict__ V, const int* __restrict__ vlen)
{
    const int bz = blockIdx.z;
    const int b  = bz >> 2;
    const int s  = bz & 3;
    const int m0 = blockIdx.x * 64;
    const int n0 = blockIdx.y * 64;
    const int vl = vlen[b];
    const int kcap = min(KN, (vl + 15) & ~15);

    const int kbeg = s * KSPLIT;
    const int kend = min(kbeg + KSPLIT, kcap);
    if (kbeg >= kend) return;

    const float* __restrict__ A  = g_scores + (size_t)b * QN * KN;
    const float* __restrict__ Bv = V + (size_t)b * KN * DD;
    float* __restrict__ C        = g_avp[s] + (size_t)b * QN * DD;

    __shared__ __align__(16) float As[16][68];
    __shared__ __align__(16) float Bs[16][68];

    const int tid = threadIdx.x;
    const int tx = tid & 15;
    const int ty = tid >> 4;

    float acc[4][4] = {};

    for (int k0 = kbeg; k0 < kend; k0 += 16) {
        {
            int row = tid >> 2;
            int c4  = tid & 3;
            float4 v = *(const float4*)&A[(size_t)(m0 + row) * KN + k0 + c4 * 4];
            As[c4 * 4 + 0][row] = v.x;
            As[c4 * 4 + 1][row] = v.y;
            As[c4 * 4 + 2][row] = v.z;
            As[c4 * 4 + 3][row] = v.w;
        }
        {
            int n4 = tid & 15;
            int kk = tid >> 4;
            float4 v = *(const float4*)&Bv[(size_t)(k0 + kk) * DD + n0 + n4 * 4];
            *(float4*)&Bs[kk][n4 * 4] = v;
        }
        __syncthreads();
        #pragma unroll
        for (int kk = 0; kk < 16; kk++) {
            float4 a = *(const float4*)&As[kk][ty * 4];
            float4 bq = *(const float4*)&Bs[kk][tx * 4];
            float av[4] = {a.x, a.y, a.z, a.w};
            float bv2[4] = {bq.x, bq.y, bq.z, bq.w};
            #pragma unroll
            for (int i = 0; i < 4; i++)
                #pragma unroll
                for (int j = 0; j < 4; j++)
                    acc[i][j] = fmaf(av[i], bv2[j], acc[i][j]);
        }
        __syncthreads();
    }

    #pragma unroll
    for (int i = 0; i < 4; i++) {
        float4 o = make_float4(acc[i][0], acc[i][1], acc[i][2], acc[i][3]);
        *(float4*)&C[(size_t)(m0 + ty * 4 + i) * DD + n0 + tx * 4] = o;
    }
}

// ---------------------------------------------------------------------------
// Reduce split-K partials into out. 65536 float4 elements total.
// ---------------------------------------------------------------------------
__global__ __launch_bounds__(256) void av_reduce(
    float* __restrict__ out, const int* __restrict__ vlen)
{
    const int idx = blockIdx.x * 256 + threadIdx.x;   // float4 index
    const int perB = QN * DD / 4;                      // 16384
    const int b = idx / perB;
    const int vl = vlen[b];
    const int ns = min(NSPLIT, (vl + KSPLIT - 1) / KSPLIT);

    float4 acc = ((const float4*)g_avp[0])[idx];
    for (int s = 1; s < ns; s++) {
        float4 p = ((const float4*)g_avp[s])[idx];
        acc.x += p.x; acc.y += p.y; acc.z += p.z; acc.w += p.w;
    }
    ((float4*)out)[idx] = acc;
}

// ---------------------------------------------------------------------------
extern "C" void kernel_launch(void* const* d_in, const int* in_sizes, int n_in,
                              void* d_out, int out_size)
{
    (void)in_sizes; (void)n_in; (void)out_size;
    const float* queries = (const float*)d_in[0];   // [4,128,512]
    const float* keys    = (const float*)d_in[1];   // [4,1024,512]
    const float* values  = (const float*)d_in[2];   // [4,1024,512]
    const int*   vlen    = (const int*)d_in[3];     // [4]
    const float* Wq      = (const float*)d_in[4];   // [512,256]
    const float* Wk      = (const float*)d_in[5];   // [512,256]
    const float* wv      = (const float*)d_in[6];   // [256]
    float* out = (float*)d_out;                     // [4,128,512]

    proj_gemm<<<dim3(72, 4), 256>>>(queries, keys, Wq, Wk, vlen);
    scores_kernel<<<dim3(8, 16, 4), 256>>>(wv, vlen);
    softmax_kernel<<<128, 128>>>(vlen);
    av_gemm<<<dim3(2, 8, 16), 256>>>(values, vlen);
    av_reduce<<<256, 256>>>(out, vlen);
}

// round 5
// speedup vs baseline: 2.3041x; 1.0841x over previous
#include <cuda_runtime.h>

#define BB 4
#define QN 128
#define KN 1024
#define DD 512     // DQ == DK == DV
#define HH 256
#define NSPLIT 8
#define KSPLIT (KN / NSPLIT)   // 128

// Scratch (allocation-free rule: __device__ globals)
__device__ float g_qp[BB * QN * HH];                 // [512][256]
__device__ float g_kp[BB * KN * HH];                 // [4096][256]
__device__ float g_scores[BB * QN * KN];             // [512][1024] -> attn in place
__device__ float g_avp[NSPLIT][BB * QN * DD];        // split-K partials, 8 MB

// ---------------------------------------------------------------------------
// Pipelined 64x64 fp32 tile-GEMM body (256 thr, 4x4/thread, K-tile 16,
// double-buffered smem, register prefetch). Shared by proj and av kernels.
//   A: [*, lda] row-major, rows m0..m0+63, k from kbeg
//   B: [*, ldb] row-major, k rows, cols n0..n0+63
// ---------------------------------------------------------------------------
struct GemmSmem {
    float As[2][16][68];
    float Bs[2][16][68];
};

__device__ __forceinline__ void gemm_tile_pipelined(
    const float* __restrict__ A, int lda,
    const float* __restrict__ B, int ldb,
    float* __restrict__ C, int ldc,
    int m0, int n0, int kbeg, int kend, GemmSmem& sm)
{
    const int tid = threadIdx.x;
    const int tx = tid & 15;        // n
    const int ty = tid >> 4;        // m
    const int arow = tid >> 2;      // 0..63  A-load row
    const int ac4  = tid & 3;       // 0..3   A-load k-quad
    const int bn4  = tid & 15;      // B-load n-quad
    const int bkk  = tid >> 4;      // B-load k row

    const int ntile = (kend - kbeg) >> 4;

    float acc[4][4] = {};
    float4 pa, pb;

    // prologue: load tile 0
    pa = *(const float4*)&A[(size_t)(m0 + arow) * lda + kbeg + ac4 * 4];
    pb = *(const float4*)&B[(size_t)(kbeg + bkk) * ldb + n0 + bn4 * 4];
    sm.As[0][ac4 * 4 + 0][arow] = pa.x;
    sm.As[0][ac4 * 4 + 1][arow] = pa.y;
    sm.As[0][ac4 * 4 + 2][arow] = pa.z;
    sm.As[0][ac4 * 4 + 3][arow] = pa.w;
    *(float4*)&sm.Bs[0][bkk][bn4 * 4] = pb;
    __syncthreads();

    int buf = 0;
    for (int t = 0; t < ntile; t++) {
        // prefetch next tile into regs
        if (t + 1 < ntile) {
            int k0 = kbeg + (t + 1) * 16;
            pa = *(const float4*)&A[(size_t)(m0 + arow) * lda + k0 + ac4 * 4];
            pb = *(const float4*)&B[(size_t)(k0 + bkk) * ldb + n0 + bn4 * 4];
        }
        // compute current tile
        #pragma unroll
        for (int kk = 0; kk < 16; kk++) {
            float4 a = *(const float4*)&sm.As[buf][kk][ty * 4];
            float4 b = *(const float4*)&sm.Bs[buf][kk][tx * 4];
            float av[4] = {a.x, a.y, a.z, a.w};
            float bv[4] = {b.x, b.y, b.z, b.w};
            #pragma unroll
            for (int i = 0; i < 4; i++)
                #pragma unroll
                for (int j = 0; j < 4; j++)
                    acc[i][j] = fmaf(av[i], bv[j], acc[i][j]);
        }
        // stage next tile into other buffer
        if (t + 1 < ntile) {
            int nb = buf ^ 1;
            sm.As[nb][ac4 * 4 + 0][arow] = pa.x;
            sm.As[nb][ac4 * 4 + 1][arow] = pa.y;
            sm.As[nb][ac4 * 4 + 2][arow] = pa.z;
            sm.As[nb][ac4 * 4 + 3][arow] = pa.w;
            *(float4*)&sm.Bs[nb][bkk][bn4 * 4] = pb;
            __syncthreads();
            buf = nb;
        }
    }

    #pragma unroll
    for (int i = 0; i < 4; i++) {
        float4 o = make_float4(acc[i][0], acc[i][1], acc[i][2], acc[i][3]);
        *(float4*)&C[(size_t)(m0 + ty * 4 + i) * ldc + n0 + tx * 4] = o;
    }
}

// ---------------------------------------------------------------------------
// Combined projection GEMM over M = 512 (queries) + 4096 (keys) rows.
// ---------------------------------------------------------------------------
__global__ __launch_bounds__(256) void proj_gemm(
    const float* __restrict__ queries, const float* __restrict__ keys,
    const float* __restrict__ Wq, const float* __restrict__ Wk,
    const int* __restrict__ vlen)
{
    const int m0g = blockIdx.x * 64;          // 0..4544
    const int n0  = blockIdx.y * 64;

    const float* A;
    const float* W;
    float* C;
    int m0;
    if (m0g < BB * QN) {
        A = queries; W = Wq; C = g_qp; m0 = m0g;
    } else {
        m0 = m0g - BB * QN;
        int b = m0 >> 10;
        if ((m0 & 1023) >= vlen[b]) return;
        A = keys; W = Wk; C = g_kp;
    }

    __shared__ __align__(16) GemmSmem sm;
    gemm_tile_pipelined(A, DD, W, HH, C, HH, m0, n0, 0, DD, sm);
}

// ---------------------------------------------------------------------------
// Scores: s[b,q,k] = sum_h wv[h] * tanh(qp[b,q,h] + kp[b,k,h])
// grid: (ktile 8) x (qtile 16) x (b 4); block 256 = 8 warps (q) x 32 lanes (k)
// ---------------------------------------------------------------------------
__global__ __launch_bounds__(256) void scores_kernel(
    const float* __restrict__ wv, const int* __restrict__ vlen)
{
    const int b  = blockIdx.z;
    const int q0 = blockIdx.y * 8;
    const int k0 = blockIdx.x * 128;
    const int vl = vlen[b];
    if (k0 >= vl) return;

    __shared__ __align__(16) float qs[8][HH];      // 8 KB
    __shared__ __align__(16) float wvs[HH];        // 1 KB
    __shared__ float kst[HH][33];                  // 33 KB, transposed k-tile

    const int tid  = threadIdx.x;
    const int lane = tid & 31;
    const int w    = tid >> 5;

    const float* qpB = g_qp + (size_t)(b * QN + q0) * HH;
    #pragma unroll
    for (int i = 0; i < 2; i++)
        ((float4*)qs)[tid + i * 256] = ((const float4*)qpB)[tid + i * 256];
    if (tid < 64)
        ((float4*)wvs)[tid] = ((const float4*)wv)[tid];

    const int q = w;
    const int k = lane;

    for (int kc = k0; kc < k0 + 128; kc += 32) {
        if (kc >= vl) break;   // uniform across block
        __syncthreads();
        const float* kpB = g_kp + (size_t)(b * KN + kc) * HH;
        {
            int kk = (lane >> 3) + 4 * w;   // 0..31
            int hb = (lane & 7);            // 0..7
            #pragma unroll
            for (int i = 0; i < 8; i++) {
                int h4 = hb + 8 * i;        // 0..63
                float4 v = ((const float4*)(kpB + (size_t)kk * HH))[h4];
                kst[h4 * 4 + 0][kk] = v.x;
                kst[h4 * 4 + 1][kk] = v.y;
                kst[h4 * 4 + 2][kk] = v.z;
                kst[h4 * 4 + 3][kk] = v.w;
            }
        }
        __syncthreads();

        float acc = 0.f;
        #pragma unroll 4
        for (int h0 = 0; h0 < HH; h0 += 8) {
            float4 a0 = *(const float4*)&qs[q][h0];
            float4 a1 = *(const float4*)&qs[q][h0 + 4];
            float4 w0 = *(const float4*)&wvs[h0];
            float4 w1 = *(const float4*)&wvs[h0 + 4];
            float av[8] = {a0.x, a0.y, a0.z, a0.w, a1.x, a1.y, a1.z, a1.w};
            float wva[8] = {w0.x, w0.y, w0.z, w0.w, w1.x, w1.y, w1.z, w1.w};
            #pragma unroll
            for (int j = 0; j < 8; j++) {
                float x = av[j] + kst[h0 + j][k];
                float t;
                asm("tanh.approx.f32 %0, %1;" : "=f"(t) : "f"(x));
                acc = fmaf(wva[j], t, acc);
            }
        }
        g_scores[(size_t)(b * QN + q0 + q) * KN + kc + k] = acc;
    }
}

// ---------------------------------------------------------------------------
// Softmax in place on g_scores (masked -> exact 0). One warp per row.
// ---------------------------------------------------------------------------
__global__ __launch_bounds__(128) void softmax_kernel(const int* __restrict__ vlen)
{
    const int row  = blockIdx.x * 4 + (threadIdx.x >> 5);   // 0..511
    const int lane = threadIdx.x & 31;
    const int b    = row >> 7;
    const int vl   = vlen[b];
    float* s = g_scores + (size_t)row * KN;

    float vals[32];
    float mx = -1e30f;
    #pragma unroll
    for (int i = 0; i < 32; i++) {
        int kk = lane + i * 32;
        float v = (kk < vl) ? s[kk] : -1e30f;
        vals[i] = v;
        mx = fmaxf(mx, v);
    }
    #pragma unroll
    for (int o = 16; o; o >>= 1) mx = fmaxf(mx, __shfl_xor_sync(0xffffffffu, mx, o));

    float sum = 0.f;
    #pragma unroll
    for (int i = 0; i < 32; i++) {
        float e = (vals[i] > -1e29f) ? __expf(vals[i] - mx) : 0.f;
        vals[i] = e;
        sum += e;
    }
    #pragma unroll
    for (int o = 16; o; o >>= 1) sum += __shfl_xor_sync(0xffffffffu, sum, o);

    float r = 1.f / sum;
    #pragma unroll
    for (int i = 0; i < 32; i++) s[lane + i * 32] = vals[i] * r;
}

// ---------------------------------------------------------------------------
// AV GEMM split-K: partial[s] = attn[b][:, s*128:(s+1)*128] @ V slice
// grid: (m 2, n 8, b*NSPLIT 32)
// ---------------------------------------------------------------------------
__global__ __launch_bounds__(256) void av_gemm(
    const float* __restrict__ V, const int* __restrict__ vlen)
{
    const int bz = blockIdx.z;
    const int b  = bz >> 3;
    const int s  = bz & 7;
    const int m0 = blockIdx.x * 64;
    const int n0 = blockIdx.y * 64;
    const int vl = vlen[b];
    const int kcap = min(KN, (vl + 15) & ~15);

    const int kbeg = s * KSPLIT;
    const int kend = min(kbeg + KSPLIT, kcap);
    if (kbeg >= kend) return;

    const float* __restrict__ A  = g_scores + (size_t)b * QN * KN;
    const float* __restrict__ Bv = V + (size_t)b * KN * DD;
    float* __restrict__ C        = g_avp[s] + (size_t)b * QN * DD;

    __shared__ __align__(16) GemmSmem sm;
    gemm_tile_pipelined(A, KN, Bv, DD, C, DD, m0, n0, kbeg, kend, sm);
}

// ---------------------------------------------------------------------------
// Reduce split-K partials into out.
// ---------------------------------------------------------------------------
__global__ __launch_bounds__(256) void av_reduce(
    float* __restrict__ out, const int* __restrict__ vlen)
{
    const int idx = blockIdx.x * 256 + threadIdx.x;   // float4 index
    const int perB = QN * DD / 4;                      // 16384
    const int b = idx / perB;
    const int vl = vlen[b];
    const int ns = min(NSPLIT, (vl + KSPLIT - 1) / KSPLIT);

    float4 acc = ((const float4*)g_avp[0])[idx];
    for (int s = 1; s < ns; s++) {
        float4 p = ((const float4*)g_avp[s])[idx];
        acc.x += p.x; acc.y += p.y; acc.z += p.z; acc.w += p.w;
    }
    ((float4*)out)[idx] = acc;
}

// ---------------------------------------------------------------------------
extern "C" void kernel_launch(void* const* d_in, const int* in_sizes, int n_in,
                              void* d_out, int out_size)
{
    (void)in_sizes; (void)n_in; (void)out_size;
    const float* queries = (const float*)d_in[0];   // [4,128,512]
    const float* keys    = (const float*)d_in[1];   // [4,1024,512]
    const float* values  = (const float*)d_in[2];   // [4,1024,512]
    const int*   vlen    = (const int*)d_in[3];     // [4]
    const float* Wq      = (const float*)d_in[4];   // [512,256]
    const float* Wk      = (const float*)d_in[5];   // [512,256]
    const float* wv      = (const float*)d_in[6];   // [256]
    float* out = (float*)d_out;                     // [4,128,512]

    proj_gemm<<<dim3(72, 4), 256>>>(queries, keys, Wq, Wk, vlen);
    scores_kernel<<<dim3(8, 16, 4), 256>>>(wv, vlen);
    softmax_kernel<<<128, 128>>>(vlen);
    av_gemm<<<dim3(2, 8, BB * NSPLIT), 256>>>(values, vlen);
    av_reduce<<<256, 256>>>(out, vlen);
}

// round 6
// speedup vs baseline: 2.3493x; 1.0196x over previous
#include <cuda_runtime.h>

#define BB 4
#define QN 128
#define KN 1024
#define DD 512     // DQ == DK == DV
#define HH 256
#define NSPLIT 8
#define KSPLIT (KN / NSPLIT)   // 128

// Scratch (allocation-free rule: __device__ globals)
__device__ float g_qp[BB * QN * HH];                 // [512][256]
__device__ float g_kp[BB * KN * HH];                 // [4096][256]
__device__ float g_scores[BB * QN * KN];             // [512][1024] -> attn in place
__device__ float g_avp[NSPLIT][BB * QN * DD];        // split-K partials, 8 MB

// ---------------------------------------------------------------------------
// Pipelined 64x64 fp32 tile-GEMM, 128 threads, 8(m)x4(n) per thread,
// K-tile 16, double-buffered smem with register prefetch.
//   A: [*, lda] row-major, rows m0..m0+63; B: [*, ldb] rows k, cols n0..n0+63
// ---------------------------------------------------------------------------
struct GemmSmem {
    float As[2][16][68];
    float Bs[2][16][68];
};

__device__ __forceinline__ void gemm64x64_t128(
    const float* __restrict__ A, int lda,
    const float* __restrict__ B, int ldb,
    float* __restrict__ C, int ldc,
    int m0, int n0, int kbeg, int kend, GemmSmem& sm)
{
    const int tid = threadIdx.x;
    const int tx = tid & 15;          // n: 4 cols each
    const int ty = tid >> 4;          // m: 8 rows each (0..7)
    const int arow = tid >> 1;        // 0..63   A-load row
    const int ac4b = tid & 1;         // A-load k-quad base (0/1), quads {b, b+2}
    const int bn4  = tid & 15;        // B-load n-quad
    const int bkkb = tid >> 4;        // B-load k row base (0..7), rows {b, b+8}

    const int ntile = (kend - kbeg) >> 4;

    float acc[8][4] = {};
    float4 pa[2], pb[2];

    // prologue: load tile 0
    {
        const float* Ar = &A[(size_t)(m0 + arow) * lda + kbeg];
        pa[0] = *(const float4*)&Ar[(ac4b + 0) * 4];
        pa[1] = *(const float4*)&Ar[(ac4b + 2) * 4];
        pb[0] = *(const float4*)&B[(size_t)(kbeg + bkkb + 0) * ldb + n0 + bn4 * 4];
        pb[1] = *(const float4*)&B[(size_t)(kbeg + bkkb + 8) * ldb + n0 + bn4 * 4];
        #pragma unroll
        for (int i = 0; i < 2; i++) {
            int c4 = ac4b + 2 * i;
            sm.As[0][c4 * 4 + 0][arow] = (&pa[i].x)[0];
            sm.As[0][c4 * 4 + 1][arow] = (&pa[i].x)[1];
            sm.As[0][c4 * 4 + 2][arow] = (&pa[i].x)[2];
            sm.As[0][c4 * 4 + 3][arow] = (&pa[i].x)[3];
            *(float4*)&sm.Bs[0][bkkb + 8 * i][bn4 * 4] = pb[i];
        }
    }
    __syncthreads();

    int buf = 0;
    for (int t = 0; t < ntile; t++) {
        if (t + 1 < ntile) {
            int k0 = kbeg + (t + 1) * 16;
            const float* Ar = &A[(size_t)(m0 + arow) * lda + k0];
            pa[0] = *(const float4*)&Ar[(ac4b + 0) * 4];
            pa[1] = *(const float4*)&Ar[(ac4b + 2) * 4];
            pb[0] = *(const float4*)&B[(size_t)(k0 + bkkb + 0) * ldb + n0 + bn4 * 4];
            pb[1] = *(const float4*)&B[(size_t)(k0 + bkkb + 8) * ldb + n0 + bn4 * 4];
        }
        #pragma unroll
        for (int kk = 0; kk < 16; kk++) {
            float4 a0 = *(const float4*)&sm.As[buf][kk][ty * 8];
            float4 a1 = *(const float4*)&sm.As[buf][kk][ty * 8 + 4];
            float4 b  = *(const float4*)&sm.Bs[buf][kk][tx * 4];
            float av[8] = {a0.x, a0.y, a0.z, a0.w, a1.x, a1.y, a1.z, a1.w};
            float bv[4] = {b.x, b.y, b.z, b.w};
            #pragma unroll
            for (int i = 0; i < 8; i++)
                #pragma unroll
                for (int j = 0; j < 4; j++)
                    acc[i][j] = fmaf(av[i], bv[j], acc[i][j]);
        }
        if (t + 1 < ntile) {
            int nb = buf ^ 1;
            #pragma unroll
            for (int i = 0; i < 2; i++) {
                int c4 = ac4b + 2 * i;
                sm.As[nb][c4 * 4 + 0][arow] = (&pa[i].x)[0];
                sm.As[nb][c4 * 4 + 1][arow] = (&pa[i].x)[1];
                sm.As[nb][c4 * 4 + 2][arow] = (&pa[i].x)[2];
                sm.As[nb][c4 * 4 + 3][arow] = (&pa[i].x)[3];
                *(float4*)&sm.Bs[nb][bkkb + 8 * i][bn4 * 4] = pb[i];
            }
            __syncthreads();
            buf = nb;
        }
    }

    #pragma unroll
    for (int i = 0; i < 8; i++) {
        float4 o = make_float4(acc[i][0], acc[i][1], acc[i][2], acc[i][3]);
        *(float4*)&C[(size_t)(m0 + ty * 8 + i) * ldc + n0 + tx * 4] = o;
    }
}

// ---------------------------------------------------------------------------
// Combined projection GEMM over M = 512 (queries) + 4096 (keys) rows.
// ---------------------------------------------------------------------------
__global__ __launch_bounds__(128) void proj_gemm(
    const float* __restrict__ queries, const float* __restrict__ keys,
    const float* __restrict__ Wq, const float* __restrict__ Wk,
    const int* __restrict__ vlen)
{
    const int m0g = blockIdx.x * 64;          // 0..4544
    const int n0  = blockIdx.y * 64;

    const float* A;
    const float* W;
    float* C;
    int m0;
    if (m0g < BB * QN) {
        A = queries; W = Wq; C = g_qp; m0 = m0g;
    } else {
        m0 = m0g - BB * QN;
        int b = m0 >> 10;
        if ((m0 & 1023) >= vlen[b]) return;
        A = keys; W = Wk; C = g_kp;
    }

    __shared__ __align__(16) GemmSmem sm;
    gemm64x64_t128(A, DD, W, HH, C, HH, m0, n0, 0, DD, sm);
}

// ---------------------------------------------------------------------------
// Scores: s[b,q,k] = sum_h wv[h] * tanh(qp[b,q,h] + kp[b,k,h])
// grid: (ktile 8) x (qtile 16) x (b 4); block 256 = 8 warps (q) x 32 lanes (k)
// k-tile transpose is software-pipelined: next chunk's LDGs issue before the
// current chunk's compute phase.
// ---------------------------------------------------------------------------
__global__ __launch_bounds__(256) void scores_kernel(
    const float* __restrict__ wv, const int* __restrict__ vlen)
{
    const int b  = blockIdx.z;
    const int q0 = blockIdx.y * 8;
    const int k0 = blockIdx.x * 128;
    const int vl = vlen[b];
    if (k0 >= vl) return;

    __shared__ __align__(16) float qs[8][HH];      // 8 KB
    __shared__ __align__(16) float wvs[HH];        // 1 KB
    __shared__ float kst[HH][33];                  // 33 KB, transposed k-tile

    const int tid  = threadIdx.x;
    const int lane = tid & 31;
    const int w    = tid >> 5;

    const float* qpB = g_qp + (size_t)(b * QN + q0) * HH;
    #pragma unroll
    for (int i = 0; i < 2; i++)
        ((float4*)qs)[tid + i * 256] = ((const float4*)qpB)[tid + i * 256];
    if (tid < 64)
        ((float4*)wvs)[tid] = ((const float4*)wv)[tid];

    const int q = w;
    const int k = lane;

    // transpose-load lane mapping
    const int tkk = (lane >> 3) + 4 * w;   // 0..31 key within chunk
    const int thb = lane & 7;              // h-quad base

    float4 pv[8];
    // prefetch chunk 0
    {
        const float* kpB = g_kp + (size_t)(b * KN + k0) * HH;
        #pragma unroll
        for (int i = 0; i < 8; i++)
            pv[i] = ((const float4*)(kpB + (size_t)tkk * HH))[thb + 8 * i];
    }

    for (int kc = k0; kc < k0 + 128; kc += 32) {
        if (kc >= vl) break;   // uniform across block
        __syncthreads();       // prior compute done reading kst
        #pragma unroll
        for (int i = 0; i < 8; i++) {
            int h4 = thb + 8 * i;
            kst[h4 * 4 + 0][tkk] = pv[i].x;
            kst[h4 * 4 + 1][tkk] = pv[i].y;
            kst[h4 * 4 + 2][tkk] = pv[i].z;
            kst[h4 * 4 + 3][tkk] = pv[i].w;
        }
        __syncthreads();

        // prefetch next chunk while computing this one
        if (kc + 32 < min(k0 + 128, vl)) {
            const float* kpB = g_kp + (size_t)(b * KN + kc + 32) * HH;
            #pragma unroll
            for (int i = 0; i < 8; i++)
                pv[i] = ((const float4*)(kpB + (size_t)tkk * HH))[thb + 8 * i];
        }

        float acc = 0.f;
        #pragma unroll 4
        for (int h0 = 0; h0 < HH; h0 += 8) {
            float4 a0 = *(const float4*)&qs[q][h0];
            float4 a1 = *(const float4*)&qs[q][h0 + 4];
            float4 w0 = *(const float4*)&wvs[h0];
            float4 w1 = *(const float4*)&wvs[h0 + 4];
            float av[8] = {a0.x, a0.y, a0.z, a0.w, a1.x, a1.y, a1.z, a1.w};
            float wva[8] = {w0.x, w0.y, w0.z, w0.w, w1.x, w1.y, w1.z, w1.w};
            #pragma unroll
            for (int j = 0; j < 8; j++) {
                float x = av[j] + kst[h0 + j][k];
                float t;
                asm("tanh.approx.f32 %0, %1;" : "=f"(t) : "f"(x));
                acc = fmaf(wva[j], t, acc);
            }
        }
        g_scores[(size_t)(b * QN + q0 + q) * KN + kc + k] = acc;
    }
}

// ---------------------------------------------------------------------------
// Softmax in place on g_scores (masked -> exact 0). One warp per row.
// ---------------------------------------------------------------------------
__global__ __launch_bounds__(128) void softmax_kernel(const int* __restrict__ vlen)
{
    const int row  = blockIdx.x * 4 + (threadIdx.x >> 5);   // 0..511
    const int lane = threadIdx.x & 31;
    const int b    = row >> 7;
    const int vl   = vlen[b];
    float* s = g_scores + (size_t)row * KN;

    float vals[32];
    float mx = -1e30f;
    #pragma unroll
    for (int i = 0; i < 32; i++) {
        int kk = lane + i * 32;
        float v = (kk < vl) ? s[kk] : -1e30f;
        vals[i] = v;
        mx = fmaxf(mx, v);
    }
    #pragma unroll
    for (int o = 16; o; o >>= 1) mx = fmaxf(mx, __shfl_xor_sync(0xffffffffu, mx, o));

    float sum = 0.f;
    #pragma unroll
    for (int i = 0; i < 32; i++) {
        float e = (vals[i] > -1e29f) ? __expf(vals[i] - mx) : 0.f;
        vals[i] = e;
        sum += e;
    }
    #pragma unroll
    for (int o = 16; o; o >>= 1) sum += __shfl_xor_sync(0xffffffffu, sum, o);

    float r = 1.f / sum;
    #pragma unroll
    for (int i = 0; i < 32; i++) s[lane + i * 32] = vals[i] * r;
}

// ---------------------------------------------------------------------------
// AV GEMM split-K: partial[s] = attn[b][:, s*128:(s+1)*128] @ V slice
// grid: (m 2, n 8, b*NSPLIT 32), 128 threads
// ---------------------------------------------------------------------------
__global__ __launch_bounds__(128) void av_gemm(
    const float* __restrict__ V, const int* __restrict__ vlen)
{
    const int bz = blockIdx.z;
    const int b  = bz >> 3;
    const int s  = bz & 7;
    const int m0 = blockIdx.x * 64;
    const int n0 = blockIdx.y * 64;
    const int vl = vlen[b];
    const int kcap = min(KN, (vl + 15) & ~15);

    const int kbeg = s * KSPLIT;
    const int kend = min(kbeg + KSPLIT, kcap);
    if (kbeg >= kend) return;

    const float* __restrict__ A  = g_scores + (size_t)b * QN * KN;
    const float* __restrict__ Bv = V + (size_t)b * KN * DD;
    float* __restrict__ C        = g_avp[s] + (size_t)b * QN * DD;

    __shared__ __align__(16) GemmSmem sm;
    gemm64x64_t128(A, KN, Bv, DD, C, DD, m0, n0, kbeg, kend, sm);
}

// ---------------------------------------------------------------------------
// Reduce split-K partials into out.
// ---------------------------------------------------------------------------
__global__ __launch_bounds__(256) void av_reduce(
    float* __restrict__ out, const int* __restrict__ vlen)
{
    const int idx = blockIdx.x * 256 + threadIdx.x;   // float4 index
    const int perB = QN * DD / 4;                      // 16384
    const int b = idx / perB;
    const int vl = vlen[b];
    const int ns = min(NSPLIT, (vl + KSPLIT - 1) / KSPLIT);

    float4 acc = ((const float4*)g_avp[0])[idx];
    for (int s = 1; s < ns; s++) {
        float4 p = ((const float4*)g_avp[s])[idx];
        acc.x += p.x; acc.y += p.y; acc.z += p.z; acc.w += p.w;
    }
    ((float4*)out)[idx] = acc;
}

// ---------------------------------------------------------------------------
extern "C" void kernel_launch(void* const* d_in, const int* in_sizes, int n_in,
                              void* d_out, int out_size)
{
    (void)in_sizes; (void)n_in; (void)out_size;
    const float* queries = (const float*)d_in[0];   // [4,128,512]
    const float* keys    = (const float*)d_in[1];   // [4,1024,512]
    const float* values  = (const float*)d_in[2];   // [4,1024,512]
    const int*   vlen    = (const int*)d_in[3];     // [4]
    const float* Wq      = (const float*)d_in[4];   // [512,256]
    const float* Wk      = (const float*)d_in[5];   // [512,256]
    const float* wv      = (const float*)d_in[6];   // [256]
    float* out = (float*)d_out;                     // [4,128,512]

    proj_gemm<<<dim3(72, 4), 128>>>(queries, keys, Wq, Wk, vlen);
    scores_kernel<<<dim3(8, 16, 4), 256>>>(wv, vlen);
    softmax_kernel<<<128, 128>>>(vlen);
    av_gemm<<<dim3(2, 8, BB * NSPLIT), 128>>>(values, vlen);
    av_reduce<<<256, 256>>>(out, vlen);
}

// round 9
// speedup vs baseline: 2.5765x; 1.0967x over previous
#include <cuda_runtime.h>
#include <cuda_bf16.h>
#include <cstdint>

#define BB 4
#define QN 128
#define KN 1024
#define DD 512     // DQ == DK == DV
#define HH 256
#define NSPLIT 8
#define KSPLIT (KN / NSPLIT)   // 128

#define MROWS (BB * QN + BB * KN)   // 4608 combined projection rows

// ---------------- Scratch (__device__ globals; no allocs allowed) ----------
__device__ float g_qp[BB * QN * HH];                 // [512][256]
__device__ float g_kp[BB * KN * HH];                 // [4096][256]
__device__ float g_scores[BB * QN * KN];             // [512][1024] -> attn in place
__device__ float g_avp[NSPLIT][BB * QN * DD];        // split-K partials

__device__ __nv_bfloat16 g_ab_hi[MROWS * DD];        // combined Q|K rows, bf16 hi
__device__ __nv_bfloat16 g_ab_lo[MROWS * DD];        // bf16 lo residual
__device__ __nv_bfloat16 g_wt_hi[2][HH * DD];        // W^T (q=0,k=1) bf16 hi  [256][512]
__device__ __nv_bfloat16 g_wt_lo[2][HH * DD];

// ---------------------------------------------------------------------------
// HMMA helpers (baseline PTX, works on plain sm_103 target)
// ---------------------------------------------------------------------------
__device__ __forceinline__ uint32_t smem_u32(const void* p) {
    uint32_t a;
    asm("{ .reg .u64 t; cvta.to.shared.u64 t, %1; cvt.u32.u64 %0, t; }" : "=r"(a) : "l"(p));
    return a;
}
__device__ __forceinline__ void ldsm_x4(uint32_t& r0, uint32_t& r1, uint32_t& r2,
                                        uint32_t& r3, uint32_t addr) {
    asm volatile("ldmatrix.sync.aligned.m8n8.x4.shared.b16 {%0,%1,%2,%3}, [%4];"
                 : "=r"(r0), "=r"(r1), "=r"(r2), "=r"(r3) : "r"(addr));
}
__device__ __forceinline__ void mma_bf16(float* d, const uint32_t* a, const uint32_t* b) {
    asm volatile(
        "mma.sync.aligned.m16n8k16.row.col.f32.bf16.bf16.f32 "
        "{%0,%1,%2,%3}, {%4,%5,%6,%7}, {%8,%9}, {%0,%1,%2,%3};"
        : "+f"(d[0]), "+f"(d[1]), "+f"(d[2]), "+f"(d[3])
        : "r"(a[0]), "r"(a[1]), "r"(a[2]), "r"(a[3]), "r"(b[0]), "r"(b[1]));
}

// ---------------------------------------------------------------------------
// Conversion: queries|keys rows -> bf16 hi/lo (combined [4608][512])
// ---------------------------------------------------------------------------
__global__ __launch_bounds__(256) void conv_ab(
    const float* __restrict__ queries, const float* __restrict__ keys)
{
    const int i4 = blockIdx.x * 256 + threadIdx.x;      // float4 index
    const int QF4 = BB * QN * DD / 4;                   // 65536
    float4 v = (i4 < QF4) ? ((const float4*)queries)[i4]
                          : ((const float4*)keys)[i4 - QF4];
    float s[4] = {v.x, v.y, v.z, v.w};
    __nv_bfloat16 h[4], l[4];
    #pragma unroll
    for (int j = 0; j < 4; j++) {
        h[j] = __float2bfloat16(s[j]);
        l[j] = __float2bfloat16(s[j] - __bfloat162float(h[j]));
    }
    __nv_bfloat162* oh = (__nv_bfloat162*)g_ab_hi;
    __nv_bfloat162* ol = (__nv_bfloat162*)g_ab_lo;
    oh[i4 * 2 + 0] = __halves2bfloat162(h[0], h[1]);
    oh[i4 * 2 + 1] = __halves2bfloat162(h[2], h[3]);
    ol[i4 * 2 + 0] = __halves2bfloat162(l[0], l[1]);
    ol[i4 * 2 + 1] = __halves2bfloat162(l[2], l[3]);
}

// ---------------------------------------------------------------------------
// Conversion: W[512][256] -> W^T bf16 hi/lo [256][512] for Wq (z=0), Wk (z=1)
// ---------------------------------------------------------------------------
__global__ __launch_bounds__(256) void conv_w(
    const float* __restrict__ Wq, const float* __restrict__ Wk)
{
    const int mat = blockIdx.z;
    const float* W = mat ? Wk : Wq;
    const int kt = blockIdx.x * 32;
    const int nt = blockIdx.y * 32;
    __shared__ float t[32][33];

    const int tx = threadIdx.x & 31;
    const int ty = threadIdx.x >> 5;       // 0..7
    #pragma unroll
    for (int i = 0; i < 4; i++) {
        int r = ty + i * 8;
        t[r][tx] = W[(size_t)(kt + r) * HH + nt + tx];
    }
    __syncthreads();
    #pragma unroll
    for (int i = 0; i < 4; i++) {
        int n = ty + i * 8;                // row of W^T
        float v = t[tx][n];
        __nv_bfloat16 h = __float2bfloat16(v);
        __nv_bfloat16 l = __float2bfloat16(v - __bfloat162float(h));
        g_wt_hi[mat][(size_t)(nt + n) * DD + kt + tx] = h;
        g_wt_lo[mat][(size_t)(nt + n) * DD + kt + tx] = l;
    }
}

// ---------------------------------------------------------------------------
// HMMA projection GEMM: C[128,64] per CTA = A[128,512] @ W^T[64,512]^T
// 3-term bf16 hi/lo split; 8 warps (4m x 2n), each 32x32 via m16n8k16.
// K chunk 16, double-buffered smem (48B row stride -> conflict-free ldmatrix).
// grid (36, 4) x 256, static smem 36 KB. One wave on 148 SMs.
// ---------------------------------------------------------------------------
#define ASTRIDE 24    // bf16 units per A/B smem row (48 B)

__global__ __launch_bounds__(256) void proj_hmma(const int* __restrict__ vlen)
{
    __shared__ __align__(16) __nv_bfloat16 sA[2][2][128 * ASTRIDE];  // [buf][hi/lo]
    __shared__ __align__(16) __nv_bfloat16 sB[2][2][64 * ASTRIDE];

    const int tid  = threadIdx.x;
    const int wid  = tid >> 5;
    const int lane = tid & 31;

    const int m0 = blockIdx.x * 128;            // combined row base
    const int n0 = blockIdx.y * 64;

    const __nv_bfloat16* wt_hi;
    const __nv_bfloat16* wt_lo;
    float* C;
    int crow;
    if (m0 < BB * QN) {
        wt_hi = g_wt_hi[0]; wt_lo = g_wt_lo[0]; C = g_qp; crow = m0;
    } else {
        int mk = m0 - BB * QN;
        int b = mk >> 10;
        if ((mk & 1023) >= vlen[b]) return;      // fully masked key tile
        wt_hi = g_wt_hi[1]; wt_lo = g_wt_lo[1]; C = g_kp; crow = mk;
    }

    const int warp_m = wid & 3;                  // 0..3 -> m offset 32*warp_m
    const int warp_n = wid >> 2;                 // 0..1 -> n offset 32*warp_n

    // global load mapping (per chunk): A all 256 threads, B split hi/lo by half
    const int arow  = tid >> 1;                  // 0..127
    const int ahalf = tid & 1;                   // 16B half of 32B row
    const int brow  = (tid & 127) >> 1;          // 0..63
    const int bterm = tid >> 7;                  // 0: hi, 1: lo

    // ldmatrix lane address components
    const int a_r  = (lane & 7) + ((lane >> 3) & 1) * 8;   // 0..15
    const int a_c  = (lane >> 4) * 8;                       // 0 / 8
    const int b_r  = (lane & 7) + ((lane >> 4) & 1) * 8;   // 0..15 (n within pair)
    const int b_c  = ((lane >> 3) & 1) * 8;                 // 0 / 8

    float acc[2][4][4] = {};
    float4 pah, pal, pbx;

    const __nv_bfloat16* wsel = bterm ? wt_lo : wt_hi;

    // prologue: chunk 0 into regs then smem buf 0
    pah = *(const float4*)&g_ab_hi[(size_t)(m0 + arow) * DD + ahalf * 8];
    pal = *(const float4*)&g_ab_lo[(size_t)(m0 + arow) * DD + ahalf * 8];
    pbx = *(const float4*)&wsel[(size_t)(n0 + brow) * DD + ahalf * 8];
    *(float4*)&sA[0][0][arow * ASTRIDE + ahalf * 8] = pah;
    *(float4*)&sA[0][1][arow * ASTRIDE + ahalf * 8] = pal;
    *(float4*)&sB[0][bterm][brow * ASTRIDE + ahalf * 8] = pbx;
    __syncthreads();

    int buf = 0;
    #pragma unroll 1
    for (int c = 0; c < 32; c++) {
        // prefetch next chunk
        if (c + 1 < 32) {
            int k0 = (c + 1) * 16;
            pah = *(const float4*)&g_ab_hi[(size_t)(m0 + arow) * DD + k0 + ahalf * 8];
            pal = *(const float4*)&g_ab_lo[(size_t)(m0 + arow) * DD + k0 + ahalf * 8];
            pbx = *(const float4*)&wsel[(size_t)(n0 + brow) * DD + k0 + ahalf * 8];
        }

        // ---- compute chunk c ----
        uint32_t Ah[2][4], Al[2][4], Bh[4][2], Bl[4][2];
        #pragma unroll
        for (int mt = 0; mt < 2; mt++) {
            uint32_t ra = smem_u32(&sA[buf][0][(warp_m * 32 + mt * 16 + a_r) * ASTRIDE + a_c]);
            ldsm_x4(Ah[mt][0], Ah[mt][1], Ah[mt][2], Ah[mt][3], ra);
            uint32_t rl = smem_u32(&sA[buf][1][(warp_m * 32 + mt * 16 + a_r) * ASTRIDE + a_c]);
            ldsm_x4(Al[mt][0], Al[mt][1], Al[mt][2], Al[mt][3], rl);
        }
        #pragma unroll
        for (int p = 0; p < 2; p++) {
            uint32_t rb = smem_u32(&sB[buf][0][(warp_n * 32 + p * 16 + b_r) * ASTRIDE + b_c]);
            ldsm_x4(Bh[p * 2][0], Bh[p * 2][1], Bh[p * 2 + 1][0], Bh[p * 2 + 1][1], rb);
            uint32_t rc = smem_u32(&sB[buf][1][(warp_n * 32 + p * 16 + b_r) * ASTRIDE + b_c]);
            ldsm_x4(Bl[p * 2][0], Bl[p * 2][1], Bl[p * 2 + 1][0], Bl[p * 2 + 1][1], rc);
        }
        #pragma unroll
        for (int mt = 0; mt < 2; mt++)
            #pragma unroll
            for (int nt = 0; nt < 4; nt++) {
                mma_bf16(acc[mt][nt], Ah[mt], Bh[nt]);
                mma_bf16(acc[mt][nt], Ah[mt], Bl[nt]);
                mma_bf16(acc[mt][nt], Al[mt], Bh[nt]);
            }

        // ---- stage chunk c+1 ----
        if (c + 1 < 32) {
            int nb = buf ^ 1;
            *(float4*)&sA[nb][0][arow * ASTRIDE + ahalf * 8] = pah;
            *(float4*)&sA[nb][1][arow * ASTRIDE + ahalf * 8] = pal;
            *(float4*)&sB[nb][bterm][brow * ASTRIDE + ahalf * 8] = pbx;
            __syncthreads();
            buf = nb;
        }
    }

    // epilogue: fragment layout -> C
    const int tq = lane >> 2;      // row within 8
    const int tr = lane & 3;       // col pair
    #pragma unroll
    for (int mt = 0; mt < 2; mt++)
        #pragma unroll
        for (int nt = 0; nt < 4; nt++) {
            int m = crow + warp_m * 32 + mt * 16 + tq;
            int n = n0 + warp_n * 32 + nt * 8 + tr * 2;
            *(float2*)&C[(size_t)m * HH + n] =
                make_float2(acc[mt][nt][0], acc[mt][nt][1]);
            *(float2*)&C[(size_t)(m + 8) * HH + n] =
                make_float2(acc[mt][nt][2], acc[mt][nt][3]);
        }
}

// ---------------------------------------------------------------------------
// Scores: s[b,q,k] = sum_h wv[h] * tanh(qp[b,q,h] + kp[b,k,h])
// ---------------------------------------------------------------------------
__global__ __launch_bounds__(256) void scores_kernel(
    const float* __restrict__ wv, const int* __restrict__ vlen)
{
    const int b  = blockIdx.z;
    const int q0 = blockIdx.y * 8;
    const int k0 = blockIdx.x * 128;
    const int vl = vlen[b];
    if (k0 >= vl) return;

    __shared__ __align__(16) float qs[8][HH];
    __shared__ __align__(16) float wvs[HH];
    __shared__ float kst[HH][33];

    const int tid  = threadIdx.x;
    const int lane = tid & 31;
    const int w    = tid >> 5;

    const float* qpB = g_qp + (size_t)(b * QN + q0) * HH;
    #pragma unroll
    for (int i = 0; i < 2; i++)
        ((float4*)qs)[tid + i * 256] = ((const float4*)qpB)[tid + i * 256];
    if (tid < 64)
        ((float4*)wvs)[tid] = ((const float4*)wv)[tid];

    const int q = w;
    const int k = lane;
    const int tkk = (lane >> 3) + 4 * w;
    const int thb = lane & 7;

    float4 pv[8];
    {
        const float* kpB = g_kp + (size_t)(b * KN + k0) * HH;
        #pragma unroll
        for (int i = 0; i < 8; i++)
            pv[i] = ((const float4*)(kpB + (size_t)tkk * HH))[thb + 8 * i];
    }

    for (int kc = k0; kc < k0 + 128; kc += 32) {
        if (kc >= vl) break;
        __syncthreads();
        #pragma unroll
        for (int i = 0; i < 8; i++) {
            int h4 = thb + 8 * i;
            kst[h4 * 4 + 0][tkk] = pv[i].x;
            kst[h4 * 4 + 1][tkk] = pv[i].y;
            kst[h4 * 4 + 2][tkk] = pv[i].z;
            kst[h4 * 4 + 3][tkk] = pv[i].w;
        }
        __syncthreads();

        if (kc + 32 < min(k0 + 128, vl)) {
            const float* kpB = g_kp + (size_t)(b * KN + kc + 32) * HH;
            #pragma unroll
            for (int i = 0; i < 8; i++)
                pv[i] = ((const float4*)(kpB + (size_t)tkk * HH))[thb + 8 * i];
        }

        float acc = 0.f;
        #pragma unroll 4
        for (int h0 = 0; h0 < HH; h0 += 8) {
            float4 a0 = *(const float4*)&qs[q][h0];
            float4 a1 = *(const float4*)&qs[q][h0 + 4];
            float4 w0 = *(const float4*)&wvs[h0];
            float4 w1 = *(const float4*)&wvs[h0 + 4];
            float av[8] = {a0.x, a0.y, a0.z, a0.w, a1.x, a1.y, a1.z, a1.w};
            float wva[8] = {w0.x, w0.y, w0.z, w0.w, w1.x, w1.y, w1.z, w1.w};
            #pragma unroll
            for (int j = 0; j < 8; j++) {
                float x = av[j] + kst[h0 + j][k];
                float t;
                asm("tanh.approx.f32 %0, %1;" : "=f"(t) : "f"(x));
                acc = fmaf(wva[j], t, acc);
            }
        }
        g_scores[(size_t)(b * QN + q0 + q) * KN + kc + k] = acc;
    }
}

// ---------------------------------------------------------------------------
// Softmax in place (masked -> exact 0). One warp per row.
// ---------------------------------------------------------------------------
__global__ __launch_bounds__(128) void softmax_kernel(const int* __restrict__ vlen)
{
    const int row  = blockIdx.x * 4 + (threadIdx.x >> 5);
    const int lane = threadIdx.x & 31;
    const int b    = row >> 7;
    const int vl   = vlen[b];
    float* s = g_scores + (size_t)row * KN;

    float vals[32];
    float mx = -1e30f;
    #pragma unroll
    for (int i = 0; i < 32; i++) {
        int kk = lane + i * 32;
        float v = (kk < vl) ? s[kk] : -1e30f;
        vals[i] = v;
        mx = fmaxf(mx, v);
    }
    #pragma unroll
    for (int o = 16; o; o >>= 1) mx = fmaxf(mx, __shfl_xor_sync(0xffffffffu, mx, o));

    float sum = 0.f;
    #pragma unroll
    for (int i = 0; i < 32; i++) {
        float e = (vals[i] > -1e29f) ? __expf(vals[i] - mx) : 0.f;
        vals[i] = e;
        sum += e;
    }
    #pragma unroll
    for (int o = 16; o; o >>= 1) sum += __shfl_xor_sync(0xffffffffu, sum, o);

    float r = 1.f / sum;
    #pragma unroll
    for (int i = 0; i < 32; i++) s[lane + i * 32] = vals[i] * r;
}

// ---------------------------------------------------------------------------
// AV GEMM split-K (R5 best config: 256 thr, 4x4/thread, pipelined)
// ---------------------------------------------------------------------------
struct GemmSmem {
    float As[2][16][68];
    float Bs[2][16][68];
};

__global__ __launch_bounds__(256) void av_gemm(
    const float* __restrict__ V, const int* __restrict__ vlen)
{
    const int bz = blockIdx.z;
    const int b  = bz >> 3;
    const int s  = bz & 7;
    const int m0 = blockIdx.x * 64;
    const int n0 = blockIdx.y * 64;
    const int vl = vlen[b];
    const int kcap = min(KN, (vl + 15) & ~15);

    const int kbeg = s * KSPLIT;
    const int kend = min(kbeg + KSPLIT, kcap);
    if (kbeg >= kend) return;

    const float* __restrict__ A  = g_scores + (size_t)b * QN * KN;
    const float* __restrict__ Bv = V + (size_t)b * KN * DD;
    float* __restrict__ C        = g_avp[s] + (size_t)b * QN * DD;

    __shared__ __align__(16) GemmSmem sm;

    const int tid = threadIdx.x;
    const int tx = tid & 15;
    const int ty = tid >> 4;
    const int arow = tid >> 2;
    const int ac4  = tid & 3;
    const int bn4  = tid & 15;
    const int bkk  = tid >> 4;

    const int ntile = (kend - kbeg) >> 4;

    float acc[4][4] = {};
    float4 pa, pb;

    pa = *(const float4*)&A[(size_t)(m0 + arow) * KN + kbeg + ac4 * 4];
    pb = *(const float4*)&Bv[(size_t)(kbeg + bkk) * DD + n0 + bn4 * 4];
    sm.As[0][ac4 * 4 + 0][arow] = pa.x;
    sm.As[0][ac4 * 4 + 1][arow] = pa.y;
    sm.As[0][ac4 * 4 + 2][arow] = pa.z;
    sm.As[0][ac4 * 4 + 3][arow] = pa.w;
    *(float4*)&sm.Bs[0][bkk][bn4 * 4] = pb;
    __syncthreads();

    int buf = 0;
    for (int t = 0; t < ntile; t++) {
        if (t + 1 < ntile) {
            int k0 = kbeg + (t + 1) * 16;
            pa = *(const float4*)&A[(size_t)(m0 + arow) * KN + k0 + ac4 * 4];
            pb = *(const float4*)&Bv[(size_t)(k0 + bkk) * DD + n0 + bn4 * 4];
        }
        #pragma unroll
        for (int kk = 0; kk < 16; kk++) {
            float4 a = *(const float4*)&sm.As[buf][kk][ty * 4];
            float4 bq = *(const float4*)&sm.Bs[buf][kk][tx * 4];
            float av[4] = {a.x, a.y, a.z, a.w};
            float bv2[4] = {bq.x, bq.y, bq.z, bq.w};
            #pragma unroll
            for (int i = 0; i < 4; i++)
                #pragma unroll
                for (int j = 0; j < 4; j++)
                    acc[i][j] = fmaf(av[i], bv2[j], acc[i][j]);
        }
        if (t + 1 < ntile) {
            int nb = buf ^ 1;
            sm.As[nb][ac4 * 4 + 0][arow] = pa.x;
            sm.As[nb][ac4 * 4 + 1][arow] = pa.y;
            sm.As[nb][ac4 * 4 + 2][arow] = pa.z;
            sm.As[nb][ac4 * 4 + 3][arow] = pa.w;
            *(float4*)&sm.Bs[nb][bkk][bn4 * 4] = pb;
            __syncthreads();
            buf = nb;
        }
    }

    #pragma unroll
    for (int i = 0; i < 4; i++) {
        float4 o = make_float4(acc[i][0], acc[i][1], acc[i][2], acc[i][3]);
        *(float4*)&C[(size_t)(m0 + ty * 4 + i) * DD + n0 + tx * 4] = o;
    }
}

// ---------------------------------------------------------------------------
// Reduce split-K partials into out.
// ---------------------------------------------------------------------------
__global__ __launch_bounds__(256) void av_reduce(
    float* __restrict__ out, const int* __restrict__ vlen)
{
    const int idx = blockIdx.x * 256 + threadIdx.x;
    const int perB = QN * DD / 4;
    const int b = idx / perB;
    const int vl = vlen[b];
    const int ns = min(NSPLIT, (vl + KSPLIT - 1) / KSPLIT);

    float4 acc = ((const float4*)g_avp[0])[idx];
    for (int s = 1; s < ns; s++) {
        float4 p = ((const float4*)g_avp[s])[idx];
        acc.x += p.x; acc.y += p.y; acc.z += p.z; acc.w += p.w;
    }
    ((float4*)out)[idx] = acc;
}

// ---------------------------------------------------------------------------
extern "C" void kernel_launch(void* const* d_in, const int* in_sizes, int n_in,
                              void* d_out, int out_size)
{
    (void)in_sizes; (void)n_in; (void)out_size;
    const float* queries = (const float*)d_in[0];   // [4,128,512]
    const float* keys    = (const float*)d_in[1];   // [4,1024,512]
    const float* values  = (const float*)d_in[2];   // [4,1024,512]
    const int*   vlen    = (const int*)d_in[3];     // [4]
    const float* Wq      = (const float*)d_in[4];   // [512,256]
    const float* Wk      = (const float*)d_in[5];   // [512,256]
    const float* wv      = (const float*)d_in[6];   // [256]
    float* out = (float*)d_out;                     // [4,128,512]

    conv_ab<<<2304, 256>>>(queries, keys);
    conv_w<<<dim3(16, 8, 2), 256>>>(Wq, Wk);
    proj_hmma<<<dim3(36, 4), 256>>>(vlen);
    scores_kernel<<<dim3(8, 16, 4), 256>>>(wv, vlen);
    softmax_kernel<<<128, 128>>>(vlen);
    av_gemm<<<dim3(2, 8, BB * NSPLIT), 256>>>(values, vlen);
    av_reduce<<<256, 256>>>(out, vlen);
}

// round 10
// speedup vs baseline: 3.2155x; 1.2480x over previous
#include <cuda_runtime.h>
#include <cuda_bf16.h>
#include <cuda_fp16.h>
#include <cstdint>

#define BB 4
#define QN 128
#define KN 1024
#define DD 512     // DQ == DK == DV
#define HH 256
#define NSPLIT 8
#define KSPLIT (KN / NSPLIT)   // 128

#define MROWS (BB * QN + BB * KN)   // 4608 combined projection rows

// ---------------- Scratch (__device__ globals; no allocs allowed) ----------
__device__ float g_scores[BB * QN * KN];             // [512][1024] -> attn in place
__device__ float g_avp[NSPLIT][BB * QN * DD];        // split-K partials

__device__ __half2 g_qp2[BB * QN * HH / 2];          // qp as h-paired half2 [512][128]
__device__ __half2 g_kp2[BB * KN * HH / 2];          // kp as h-paired half2 [4096][128]

__device__ __nv_bfloat16 g_ab_hi[MROWS * DD];        // combined Q|K rows, bf16 hi
__device__ __nv_bfloat16 g_ab_lo[MROWS * DD];        // bf16 lo residual
__device__ __nv_bfloat16 g_wt_hi[2][HH * DD];        // W^T (q=0,k=1) bf16 hi  [256][512]
__device__ __nv_bfloat16 g_wt_lo[2][HH * DD];

// ---------------------------------------------------------------------------
// HMMA helpers (baseline PTX, works on plain sm_103 target)
// ---------------------------------------------------------------------------
__device__ __forceinline__ uint32_t smem_u32(const void* p) {
    uint32_t a;
    asm("{ .reg .u64 t; cvta.to.shared.u64 t, %1; cvt.u32.u64 %0, t; }" : "=r"(a) : "l"(p));
    return a;
}
__device__ __forceinline__ void ldsm_x4(uint32_t& r0, uint32_t& r1, uint32_t& r2,
                                        uint32_t& r3, uint32_t addr) {
    asm volatile("ldmatrix.sync.aligned.m8n8.x4.shared.b16 {%0,%1,%2,%3}, [%4];"
                 : "=r"(r0), "=r"(r1), "=r"(r2), "=r"(r3) : "r"(addr));
}
__device__ __forceinline__ void mma_bf16(float* d, const uint32_t* a, const uint32_t* b) {
    asm volatile(
        "mma.sync.aligned.m16n8k16.row.col.f32.bf16.bf16.f32 "
        "{%0,%1,%2,%3}, {%4,%5,%6,%7}, {%8,%9}, {%0,%1,%2,%3};"
        : "+f"(d[0]), "+f"(d[1]), "+f"(d[2]), "+f"(d[3])
        : "r"(a[0]), "r"(a[1]), "r"(a[2]), "r"(a[3]), "r"(b[0]), "r"(b[1]));
}

// ---------------------------------------------------------------------------
// Conversion: queries|keys rows -> bf16 hi/lo (combined [4608][512])
// ---------------------------------------------------------------------------
__global__ __launch_bounds__(256) void conv_ab(
    const float* __restrict__ queries, const float* __restrict__ keys)
{
    const int i4 = blockIdx.x * 256 + threadIdx.x;      // float4 index
    const int QF4 = BB * QN * DD / 4;                   // 65536
    float4 v = (i4 < QF4) ? ((const float4*)queries)[i4]
                          : ((const float4*)keys)[i4 - QF4];
    float s[4] = {v.x, v.y, v.z, v.w};
    __nv_bfloat16 h[4], l[4];
    #pragma unroll
    for (int j = 0; j < 4; j++) {
        h[j] = __float2bfloat16(s[j]);
        l[j] = __float2bfloat16(s[j] - __bfloat162float(h[j]));
    }
    __nv_bfloat162* oh = (__nv_bfloat162*)g_ab_hi;
    __nv_bfloat162* ol = (__nv_bfloat162*)g_ab_lo;
    oh[i4 * 2 + 0] = __halves2bfloat162(h[0], h[1]);
    oh[i4 * 2 + 1] = __halves2bfloat162(h[2], h[3]);
    ol[i4 * 2 + 0] = __halves2bfloat162(l[0], l[1]);
    ol[i4 * 2 + 1] = __halves2bfloat162(l[2], l[3]);
}

// ---------------------------------------------------------------------------
// Conversion: W[512][256] -> W^T bf16 hi/lo [256][512] for Wq (z=0), Wk (z=1)
// ---------------------------------------------------------------------------
__global__ __launch_bounds__(256) void conv_w(
    const float* __restrict__ Wq, const float* __restrict__ Wk)
{
    const int mat = blockIdx.z;
    const float* W = mat ? Wk : Wq;
    const int kt = blockIdx.x * 32;
    const int nt = blockIdx.y * 32;
    __shared__ float t[32][33];

    const int tx = threadIdx.x & 31;
    const int ty = threadIdx.x >> 5;       // 0..7
    #pragma unroll
    for (int i = 0; i < 4; i++) {
        int r = ty + i * 8;
        t[r][tx] = W[(size_t)(kt + r) * HH + nt + tx];
    }
    __syncthreads();
    #pragma unroll
    for (int i = 0; i < 4; i++) {
        int n = ty + i * 8;                // row of W^T
        float v = t[tx][n];
        __nv_bfloat16 h = __float2bfloat16(v);
        __nv_bfloat16 l = __float2bfloat16(v - __bfloat162float(h));
        g_wt_hi[mat][(size_t)(nt + n) * DD + kt + tx] = h;
        g_wt_lo[mat][(size_t)(nt + n) * DD + kt + tx] = l;
    }
}

// ---------------------------------------------------------------------------
// HMMA projection GEMM: [128,64] tile per CTA, 3-term bf16 hi/lo split.
// Epilogue writes h-paired half2 directly to g_qp2 / g_kp2.
// grid (36, 4) x 256. One wave on 148 SMs.
// ---------------------------------------------------------------------------
#define ASTRIDE 24    // bf16 units per A/B smem row (48 B)

__global__ __launch_bounds__(256) void proj_hmma(const int* __restrict__ vlen)
{
    __shared__ __align__(16) __nv_bfloat16 sA[2][2][128 * ASTRIDE];  // [buf][hi/lo]
    __shared__ __align__(16) __nv_bfloat16 sB[2][2][64 * ASTRIDE];

    const int tid  = threadIdx.x;
    const int wid  = tid >> 5;
    const int lane = tid & 31;

    const int m0 = blockIdx.x * 128;            // combined row base
    const int n0 = blockIdx.y * 64;

    const __nv_bfloat16* wt_hi;
    const __nv_bfloat16* wt_lo;
    __half2* C2;
    int crow;
    if (m0 < BB * QN) {
        wt_hi = g_wt_hi[0]; wt_lo = g_wt_lo[0]; C2 = g_qp2; crow = m0;
    } else {
        int mk = m0 - BB * QN;
        int b = mk >> 10;
        if ((mk & 1023) >= vlen[b]) return;      // fully masked key tile
        wt_hi = g_wt_hi[1]; wt_lo = g_wt_lo[1]; C2 = g_kp2; crow = mk;
    }

    const int warp_m = wid & 3;
    const int warp_n = wid >> 2;

    const int arow  = tid >> 1;
    const int ahalf = tid & 1;
    const int brow  = (tid & 127) >> 1;
    const int bterm = tid >> 7;

    const int a_r  = (lane & 7) + ((lane >> 3) & 1) * 8;
    const int a_c  = (lane >> 4) * 8;
    const int b_r  = (lane & 7) + ((lane >> 4) & 1) * 8;
    const int b_c  = ((lane >> 3) & 1) * 8;

    float acc[2][4][4] = {};
    float4 pah, pal, pbx;

    const __nv_bfloat16* wsel = bterm ? wt_lo : wt_hi;

    pah = *(const float4*)&g_ab_hi[(size_t)(m0 + arow) * DD + ahalf * 8];
    pal = *(const float4*)&g_ab_lo[(size_t)(m0 + arow) * DD + ahalf * 8];
    pbx = *(const float4*)&wsel[(size_t)(n0 + brow) * DD + ahalf * 8];
    *(float4*)&sA[0][0][arow * ASTRIDE + ahalf * 8] = pah;
    *(float4*)&sA[0][1][arow * ASTRIDE + ahalf * 8] = pal;
    *(float4*)&sB[0][bterm][brow * ASTRIDE + ahalf * 8] = pbx;
    __syncthreads();

    int buf = 0;
    #pragma unroll 1
    for (int c = 0; c < 32; c++) {
        if (c + 1 < 32) {
            int k0 = (c + 1) * 16;
            pah = *(const float4*)&g_ab_hi[(size_t)(m0 + arow) * DD + k0 + ahalf * 8];
            pal = *(const float4*)&g_ab_lo[(size_t)(m0 + arow) * DD + k0 + ahalf * 8];
            pbx = *(const float4*)&wsel[(size_t)(n0 + brow) * DD + k0 + ahalf * 8];
        }

        uint32_t Ah[2][4], Al[2][4], Bh[4][2], Bl[4][2];
        #pragma unroll
        for (int mt = 0; mt < 2; mt++) {
            uint32_t ra = smem_u32(&sA[buf][0][(warp_m * 32 + mt * 16 + a_r) * ASTRIDE + a_c]);
            ldsm_x4(Ah[mt][0], Ah[mt][1], Ah[mt][2], Ah[mt][3], ra);
            uint32_t rl = smem_u32(&sA[buf][1][(warp_m * 32 + mt * 16 + a_r) * ASTRIDE + a_c]);
            ldsm_x4(Al[mt][0], Al[mt][1], Al[mt][2], Al[mt][3], rl);
        }
        #pragma unroll
        for (int p = 0; p < 2; p++) {
            uint32_t rb = smem_u32(&sB[buf][0][(warp_n * 32 + p * 16 + b_r) * ASTRIDE + b_c]);
            ldsm_x4(Bh[p * 2][0], Bh[p * 2][1], Bh[p * 2 + 1][0], Bh[p * 2 + 1][1], rb);
            uint32_t rc = smem_u32(&sB[buf][1][(warp_n * 32 + p * 16 + b_r) * ASTRIDE + b_c]);
            ldsm_x4(Bl[p * 2][0], Bl[p * 2][1], Bl[p * 2 + 1][0], Bl[p * 2 + 1][1], rc);
        }
        #pragma unroll
        for (int mt = 0; mt < 2; mt++)
            #pragma unroll
            for (int nt = 0; nt < 4; nt++) {
                mma_bf16(acc[mt][nt], Ah[mt], Bh[nt]);
                mma_bf16(acc[mt][nt], Ah[mt], Bl[nt]);
                mma_bf16(acc[mt][nt], Al[mt], Bh[nt]);
            }

        if (c + 1 < 32) {
            int nb = buf ^ 1;
            *(float4*)&sA[nb][0][arow * ASTRIDE + ahalf * 8] = pah;
            *(float4*)&sA[nb][1][arow * ASTRIDE + ahalf * 8] = pal;
            *(float4*)&sB[nb][bterm][brow * ASTRIDE + ahalf * 8] = pbx;
            __syncthreads();
            buf = nb;
        }
    }

    // epilogue: pack adjacent-col pairs to half2 (cols of d0/d1 are h, h+1)
    const int tq = lane >> 2;
    const int tr = lane & 3;
    #pragma unroll
    for (int mt = 0; mt < 2; mt++)
        #pragma unroll
        for (int nt = 0; nt < 4; nt++) {
            int m = crow + warp_m * 32 + mt * 16 + tq;
            int hp = (n0 + warp_n * 32 + nt * 8 + tr * 2) >> 1;
            C2[(size_t)m * (HH / 2) + hp] =
                __floats2half2_rn(acc[mt][nt][0], acc[mt][nt][1]);
            C2[(size_t)(m + 8) * (HH / 2) + hp] =
                __floats2half2_rn(acc[mt][nt][2], acc[mt][nt][3]);
        }
}

// ---------------------------------------------------------------------------
// Scores (f16x2): s[b,q,k] = sum_h wv[h] * tanh(qp[b,q,h] + kp[b,k,h])
// block 256 = 8 warps (one q each), lanes cover 64 k (2 per lane).
// grid: (k 16, q 16, b 4). tanh.approx.f16x2 doubles MUFU rate; half2 h-pair
// packing cuts smem traffic ~2.4x (old version was LDS-crossbar-bound).
// ---------------------------------------------------------------------------
__global__ __launch_bounds__(256) void scores_kernel(
    const float* __restrict__ wv, const int* __restrict__ vlen)
{
    const int b  = blockIdx.z;
    const int q0 = blockIdx.y * 8;
    const int k0 = blockIdx.x * 64;
    const int vl = vlen[b];
    if (k0 >= vl) return;

    __shared__ __half2 qs2[8][128];    // 4 KB
    __shared__ float2  wvf[128];       // 1 KB
    __shared__ __half2 kst[128][66];   // ~33.8 KB, transposed [h-pair][k], pad 66

    const int tid  = threadIdx.x;
    const int lane = tid & 31;
    const int w    = tid >> 5;

    // load qs2 (1024 half2)
    const uint32_t* qp2 = (const uint32_t*)(g_qp2 + (size_t)(b * QN + q0) * 128);
    #pragma unroll
    for (int i = 0; i < 4; i++)
        ((uint32_t*)qs2)[tid + i * 256] = qp2[tid + i * 256];
    if (tid < 128) wvf[tid] = make_float2(wv[2 * tid], wv[2 * tid + 1]);

    // transposed kst load: 64 k-rows x 128 h-pairs
    {
        const __half2* kp2 = g_kp2 + (size_t)(b * KN + k0) * 128;
        const int kk = tid >> 2;               // 0..63
        const int q8 = tid & 3;                // quad base
        #pragma unroll
        for (int j = 0; j < 8; j++) {
            int hpq = q8 + j * 4;              // 0..31
            float4 v = ((const float4*)(kp2 + (size_t)kk * 128))[hpq];
            const __half2* pv = (const __half2*)&v;
            #pragma unroll
            for (int r = 0; r < 4; r++)
                kst[hpq * 4 + r][kk] = pv[r];
        }
    }
    __syncthreads();

    const int q = w;
    float acc0 = 0.f, acc1 = 0.f, acc2 = 0.f, acc3 = 0.f;
    #pragma unroll 4
    for (int hp = 0; hp < 128; hp++) {
        __half2 qv = qs2[q][hp];
        float2 wvp = wvf[hp];
        __half2 xa = __hadd2(qv, kst[hp][lane]);
        __half2 xb = __hadd2(qv, kst[hp][lane + 32]);
        uint32_t ta, tb;
        asm("tanh.approx.f16x2 %0, %1;" : "=r"(ta) : "r"(*(uint32_t*)&xa));
        asm("tanh.approx.f16x2 %0, %1;" : "=r"(tb) : "r"(*(uint32_t*)&xb));
        float2 fa = __half22float2(*(__half2*)&ta);
        float2 fb = __half22float2(*(__half2*)&tb);
        acc0 = fmaf(wvp.x, fa.x, acc0);
        acc1 = fmaf(wvp.y, fa.y, acc1);
        acc2 = fmaf(wvp.x, fb.x, acc2);
        acc3 = fmaf(wvp.y, fb.y, acc3);
    }
    size_t row = (size_t)(b * QN + q0 + q) * KN;
    g_scores[row + k0 + lane]      = acc0 + acc1;
    g_scores[row + k0 + lane + 32] = acc2 + acc3;
}

// ---------------------------------------------------------------------------
// Softmax in place (masked -> exact 0). One warp per row.
// ---------------------------------------------------------------------------
__global__ __launch_bounds__(128) void softmax_kernel(const int* __restrict__ vlen)
{
    const int row  = blockIdx.x * 4 + (threadIdx.x >> 5);
    const int lane = threadIdx.x & 31;
    const int b    = row >> 7;
    const int vl   = vlen[b];
    float* s = g_scores + (size_t)row * KN;

    float vals[32];
    float mx = -1e30f;
    #pragma unroll
    for (int i = 0; i < 32; i++) {
        int kk = lane + i * 32;
        float v = (kk < vl) ? s[kk] : -1e30f;
        vals[i] = v;
        mx = fmaxf(mx, v);
    }
    #pragma unroll
    for (int o = 16; o; o >>= 1) mx = fmaxf(mx, __shfl_xor_sync(0xffffffffu, mx, o));

    float sum = 0.f;
    #pragma unroll
    for (int i = 0; i < 32; i++) {
        float e = (vals[i] > -1e29f) ? __expf(vals[i] - mx) : 0.f;
        vals[i] = e;
        sum += e;
    }
    #pragma unroll
    for (int o = 16; o; o >>= 1) sum += __shfl_xor_sync(0xffffffffu, sum, o);

    float r = 1.f / sum;
    #pragma unroll
    for (int i = 0; i < 32; i++) s[lane + i * 32] = vals[i] * r;
}

// ---------------------------------------------------------------------------
// AV GEMM split-K (R5 best config: 256 thr, 4x4/thread, pipelined)
// ---------------------------------------------------------------------------
struct GemmSmem {
    float As[2][16][68];
    float Bs[2][16][68];
};

__global__ __launch_bounds__(256) void av_gemm(
    const float* __restrict__ V, const int* __restrict__ vlen)
{
    const int bz = blockIdx.z;
    const int b  = bz >> 3;
    const int s  = bz & 7;
    const int m0 = blockIdx.x * 64;
    const int n0 = blockIdx.y * 64;
    const int vl = vlen[b];
    const int kcap = min(KN, (vl + 15) & ~15);

    const int kbeg = s * KSPLIT;
    const int kend = min(kbeg + KSPLIT, kcap);
    if (kbeg >= kend) return;

    const float* __restrict__ A  = g_scores + (size_t)b * QN * KN;
    const float* __restrict__ Bv = V + (size_t)b * KN * DD;
    float* __restrict__ C        = g_avp[s] + (size_t)b * QN * DD;

    __shared__ __align__(16) GemmSmem sm;

    const int tid = threadIdx.x;
    const int tx = tid & 15;
    const int ty = tid >> 4;
    const int arow = tid >> 2;
    const int ac4  = tid & 3;
    const int bn4  = tid & 15;
    const int bkk  = tid >> 4;

    const int ntile = (kend - kbeg) >> 4;

    float acc[4][4] = {};
    float4 pa, pb;

    pa = *(const float4*)&A[(size_t)(m0 + arow) * KN + kbeg + ac4 * 4];
    pb = *(const float4*)&Bv[(size_t)(kbeg + bkk) * DD + n0 + bn4 * 4];
    sm.As[0][ac4 * 4 + 0][arow] = pa.x;
    sm.As[0][ac4 * 4 + 1][arow] = pa.y;
    sm.As[0][ac4 * 4 + 2][arow] = pa.z;
    sm.As[0][ac4 * 4 + 3][arow] = pa.w;
    *(float4*)&sm.Bs[0][bkk][bn4 * 4] = pb;
    __syncthreads();

    int buf = 0;
    for (int t = 0; t < ntile; t++) {
        if (t + 1 < ntile) {
            int k0 = kbeg + (t + 1) * 16;
            pa = *(const float4*)&A[(size_t)(m0 + arow) * KN + k0 + ac4 * 4];
            pb = *(const float4*)&Bv[(size_t)(k0 + bkk) * DD + n0 + bn4 * 4];
        }
        #pragma unroll
        for (int kk = 0; kk < 16; kk++) {
            float4 a = *(const float4*)&sm.As[buf][kk][ty * 4];
            float4 bq = *(const float4*)&sm.Bs[buf][kk][tx * 4];
            float av[4] = {a.x, a.y, a.z, a.w};
            float bv2[4] = {bq.x, bq.y, bq.z, bq.w};
            #pragma unroll
            for (int i = 0; i < 4; i++)
                #pragma unroll
                for (int j = 0; j < 4; j++)
                    acc[i][j] = fmaf(av[i], bv2[j], acc[i][j]);
        }
        if (t + 1 < ntile) {
            int nb = buf ^ 1;
            sm.As[nb][ac4 * 4 + 0][arow] = pa.x;
            sm.As[nb][ac4 * 4 + 1][arow] = pa.y;
            sm.As[nb][ac4 * 4 + 2][arow] = pa.z;
            sm.As[nb][ac4 * 4 + 3][arow] = pa.w;
            *(float4*)&sm.Bs[nb][bkk][bn4 * 4] = pb;
            __syncthreads();
            buf = nb;
        }
    }

    #pragma unroll
    for (int i = 0; i < 4; i++) {
        float4 o = make_float4(acc[i][0], acc[i][1], acc[i][2], acc[i][3]);
        *(float4*)&C[(size_t)(m0 + ty * 4 + i) * DD + n0 + tx * 4] = o;
    }
}

// ---------------------------------------------------------------------------
// Reduce split-K partials into out.
// ---------------------------------------------------------------------------
__global__ __launch_bounds__(256) void av_reduce(
    float* __restrict__ out, const int* __restrict__ vlen)
{
    const int idx = blockIdx.x * 256 + threadIdx.x;
    const int perB = QN * DD / 4;
    const int b = idx / perB;
    const int vl = vlen[b];
    const int ns = min(NSPLIT, (vl + KSPLIT - 1) / KSPLIT);

    float4 acc = ((const float4*)g_avp[0])[idx];
    for (int s = 1; s < ns; s++) {
        float4 p = ((const float4*)g_avp[s])[idx];
        acc.x += p.x; acc.y += p.y; acc.z += p.z; acc.w += p.w;
    }
    ((float4*)out)[idx] = acc;
}

// ---------------------------------------------------------------------------
extern "C" void kernel_launch(void* const* d_in, const int* in_sizes, int n_in,
                              void* d_out, int out_size)
{
    (void)in_sizes; (void)n_in; (void)out_size;
    const float* queries = (const float*)d_in[0];   // [4,128,512]
    const float* keys    = (const float*)d_in[1];   // [4,1024,512]
    const float* values  = (const float*)d_in[2];   // [4,1024,512]
    const int*   vlen    = (const int*)d_in[3];     // [4]
    const float* Wq      = (const float*)d_in[4];   // [512,256]
    const float* Wk      = (const float*)d_in[5];   // [512,256]
    const float* wv      = (const float*)d_in[6];   // [256]
    float* out = (float*)d_out;                     // [4,128,512]

    conv_ab<<<2304, 256>>>(queries, keys);
    conv_w<<<dim3(16, 8, 2), 256>>>(Wq, Wk);
    proj_hmma<<<dim3(36, 4), 256>>>(vlen);
    scores_kernel<<<dim3(16, 16, 4), 256>>>(wv, vlen);
    softmax_kernel<<<128, 128>>>(vlen);
    av_gemm<<<dim3(2, 8, BB * NSPLIT), 256>>>(values, vlen);
    av_reduce<<<256, 256>>>(out, vlen);
}